// round 1
// baseline (speedup 1.0000x reference)
#include <cuda_runtime.h>
#include <math.h>

#define NP2 64
#define NV  32768
#define WARPS_PER_BLOCK 8

// Per-pulse RF rotation coefficients (written by precompute kernel).
// c0 = {ca2, ca, r10r, r10i}, c1 = {wr, wi, 0.5*wr, 0.5*wi}
__device__ float4 g_c0[NP2];
__device__ float4 g_c1[NP2];

__global__ void precompute_coef_kernel(const float* __restrict__ thr,
                                       const float* __restrict__ thi) {
    int p = threadIdx.x;
    if (p >= NP2) return;
    float tr = thr[p], ti = thi[p];
    float a  = sqrtf(tr * tr + ti * ti);     // |theta| in (0.1, pi/2): never 0
    float inv_a = 1.0f / a;
    float cphi = tr * inv_a, sphi = ti * inv_a;
    float ca, sa;
    sincosf(a, &sa, &ca);
    float ca2 = 0.5f * (1.0f + ca);          // cos^2(a/2)
    float sa2 = 0.5f * (1.0f - ca);          // sin^2(a/2)
    // e^{-2i phi} = (cphi - i sphi)^2
    float c2 =  cphi * cphi - sphi * sphi;
    float s2 =  2.0f * cphi * sphi;
    float r10r =  c2 * sa2;
    float r10i = -s2 * sa2;
    float wr = cphi * sa, wi = sphi * sa;    // w = e^{i phi} * sin(a)
    g_c0[p] = make_float4(ca2, ca, r10r, r10i);
    g_c1[p] = make_float4(wr, wi, 0.5f * wr, 0.5f * wi);
}

// Warp-per-voxel EPG recurrence. lane = k-state order (0..31).
// State per lane: F+ (Pr,Pi), F- (Mr,Mi), Z (Zr,Zi).
__global__ __launch_bounds__(WARPS_PER_BLOCK * 32)
void epg_kernel(const float* __restrict__ qmaps,   // [3, V]: PD, T1, T2
                const float* __restrict__ TRp,
                float* __restrict__ out) {          // [V, NP2]
    __shared__ float2 f0s[WARPS_PER_BLOCK][NP2];

    const int lane = threadIdx.x & 31;
    const int wid  = threadIdx.x >> 5;
    const int v    = blockIdx.x * WARPS_PER_BLOCK + wid;

    const float TR = TRp[0];
    const float t1 = qmaps[NV + v];
    const float t2 = qmaps[2 * NV + v];
    const float E1 = __expf(-TR / t1);
    const float E2 = __expf(-TR / t2);
    const float rec = (lane == 0) ? (1.0f - E1) : 0.0f;

    float Pr = 0.f, Pi = 0.f, Mr = 0.f, Mi = 0.f;
    float Zr = (lane == 0) ? 1.0f : 0.0f, Zi = 0.f;

    const bool l0  = (lane == 0);
    const bool l31 = (lane == 31);

    #pragma unroll 8
    for (int p = 0; p < NP2; p++) {
        const float4 c0 = g_c0[p];
        const float4 c1 = g_c1[p];
        const float ca2 = c0.x, ca = c0.y, r10r = c0.z, r10i = c0.w;
        const float wr = c1.x, wi = c1.y, hwr = c1.z, hwi = c1.w;

        // tmp = A @ state  (30 FFMA using matrix structure)
        float tPr = ca2 * Pr + r10r * Mr + r10i * Mi + wi * Zr + wr * Zi;
        float tPi = ca2 * Pi + r10r * Mi - r10i * Mr + wi * Zi - wr * Zr;
        float tMr = r10r * Pr - r10i * Pi + ca2 * Mr + wi * Zr - wr * Zi;
        float tMi = r10r * Pi + r10i * Pr + ca2 * Mi + wr * Zr + wi * Zi;
        float tZr = ca * Zr - hwi * Pr + hwr * Pi - hwi * Mr - hwr * Mi;
        float tZi = ca * Zi - hwr * Pr - hwi * Pi + hwr * Mr - hwi * Mi;

        // F0 signal for this pulse = tP at k=0 (before relax/shift)
        if (l0) f0s[wid][p] = make_float2(tPr, tPi);

        // EPG shift via lane shuffles:
        //   F+_k <- F+_{k-1} (shfl_up), F-_k <- F-_{k+1} (shfl_down)
        //   F+_0 <- conj(F-_1), F-_31 <- 0, Z stays.
        float pur = __shfl_up_sync(0xffffffffu, tPr, 1);
        float pui = __shfl_up_sync(0xffffffffu, tPi, 1);
        float mdr = __shfl_down_sync(0xffffffffu, tMr, 1);
        float mdi = __shfl_down_sync(0xffffffffu, tMi, 1);

        Pr = E2 * (l0 ? mdr : pur);
        Pi = E2 * (l0 ? -mdi : pui);
        Mr = l31 ? 0.0f : E2 * mdr;
        Mi = l31 ? 0.0f : E2 * mdi;
        Zr = fmaf(E1, tZr, rec);
        Zi = E1 * tZi;
    }

    __syncwarp();

    // Epilogue: |F0| * PD, coalesced 128B stores (32 lanes x 2 iters)
    const float pd = qmaps[v];
    #pragma unroll
    for (int j = 0; j < NP2 / 32; j++) {
        const int idx = j * 32 + lane;
        float2 f = f0s[wid][idx];
        out[v * NP2 + idx] = sqrtf(f.x * f.x + f.y * f.y) * pd;
    }
}

extern "C" void kernel_launch(void* const* d_in, const int* in_sizes, int n_in,
                              void* d_out, int out_size) {
    const float* theta_re = (const float*)d_in[0];   // [64]
    const float* theta_im = (const float*)d_in[1];   // [64]
    const float* TR       = (const float*)d_in[2];   // [1]
    const float* qmaps    = (const float*)d_in[3];   // [3, 32768, 1]
    float* out = (float*)d_out;                      // [32768, 64]

    precompute_coef_kernel<<<1, 64>>>(theta_re, theta_im);
    epg_kernel<<<NV / WARPS_PER_BLOCK, WARPS_PER_BLOCK * 32>>>(qmaps, TR, out);
}

// round 2
// speedup vs baseline: 1.2366x; 1.2366x over previous
#include <cuda_runtime.h>
#include <math.h>

#define NP2 64
#define NV  32768
#define WPB 8            // warps per block
#define VPW 4            // voxels per warp
#define LPV 8            // lanes per voxel
// k-states per lane = 4 (two f32x2 pairs per component); LPV*4 = 32 k-states

typedef unsigned long long u64;

// Per-pulse RF rotation coefficients (written by precompute kernel).
// c0 = {ca2, ca, r10r, r10i}, c1 = {wr, wi, 0.5*wr, 0.5*wi}
__device__ float4 g_c0[NP2];
__device__ float4 g_c1[NP2];

__global__ void precompute_coef_kernel(const float* __restrict__ thr,
                                       const float* __restrict__ thi) {
    int p = threadIdx.x;
    if (p >= NP2) return;
    float tr = thr[p], ti = thi[p];
    float a  = sqrtf(tr * tr + ti * ti);     // |theta| in (0.1, pi/2): never 0
    float inv_a = 1.0f / a;
    float cphi = tr * inv_a, sphi = ti * inv_a;
    float ca, sa;
    sincosf(a, &sa, &ca);
    float ca2 = 0.5f * (1.0f + ca);          // cos^2(a/2)
    float sa2 = 0.5f * (1.0f - ca);          // sin^2(a/2)
    float c2 =  cphi * cphi - sphi * sphi;   // e^{-2i phi} = (cphi - i sphi)^2
    float s2 =  2.0f * cphi * sphi;
    float r10r =  c2 * sa2;
    float r10i = -s2 * sa2;
    float wr = cphi * sa, wi = sphi * sa;    // w = e^{i phi} * sin(a)
    g_c0[p] = make_float4(ca2, ca, r10r, r10i);
    g_c1[p] = make_float4(wr, wi, 0.5f * wr, 0.5f * wi);
}

// ---- packed f32x2 helpers (Blackwell 2x FP32 path) ----
__device__ __forceinline__ u64 bc(float x) {
    u64 r; asm("mov.b64 %0,{%1,%1};" : "=l"(r) : "f"(x)); return r;
}
__device__ __forceinline__ u64 pk(float a, float b) {
    u64 r; asm("mov.b64 %0,{%1,%2};" : "=l"(r) : "f"(a), "f"(b)); return r;
}
__device__ __forceinline__ void up(u64 v, float& a, float& b) {
    asm("mov.b64 {%0,%1},%2;" : "=f"(a), "=f"(b) : "l"(v));
}
__device__ __forceinline__ u64 f2(u64 a, u64 b, u64 c) {
    u64 d; asm("fma.rn.f32x2 %0,%1,%2,%3;" : "=l"(d) : "l"(a), "l"(b), "l"(c)); return d;
}
__device__ __forceinline__ u64 m2(u64 a, u64 b) {
    u64 d; asm("mul.rn.f32x2 %0,%1,%2;" : "=l"(d) : "l"(a), "l"(b)); return d;
}

// Complex 3x3 EPG matvec on a packed pair of k-states (suffix S in {a,b}).
#define MATVEC(S) \
  u64 tPr_##S = f2(Cca2,Pr_##S, f2(Cr10r,Mr_##S, f2(Cr10i ,Mi_##S, f2(Cwi,Zr_##S, m2(Cwr ,Zi_##S))))); \
  u64 tPi_##S = f2(Cca2,Pi_##S, f2(Cr10r,Mi_##S, f2(Cnr10i,Mr_##S, f2(Cwi,Zi_##S, m2(Cnwr,Zr_##S))))); \
  u64 tMr_##S = f2(Cr10r,Pr_##S, f2(Cnr10i,Pi_##S, f2(Cca2,Mr_##S, f2(Cwi,Zr_##S, m2(Cnwr,Zi_##S))))); \
  u64 tMi_##S = f2(Cr10r,Pi_##S, f2(Cr10i ,Pr_##S, f2(Cca2,Mi_##S, f2(Cwr,Zr_##S, m2(Cwi ,Zi_##S))))); \
  u64 tZr_##S = f2(Cca ,Zr_##S, f2(Cnhwi,Pr_##S, f2(Chwr ,Pi_##S, f2(Cnhwi,Mr_##S, m2(Cnhwr,Mi_##S))))); \
  u64 tZi_##S = f2(Cca ,Zi_##S, f2(Cnhwr,Pr_##S, f2(Cnhwi,Pi_##S, f2(Chwr ,Mr_##S, m2(Cnhwi,Mi_##S)))));

// 4 voxels per warp, 8 lanes per voxel, 4 k-states per lane:
// lane ll (0..7) holds k = 4*ll + {0,1,2,3}; pair a = (k0,k1), pair b = (k2,k3).
__global__ __launch_bounds__(WPB * 32)
void epg_kernel(const float* __restrict__ qmaps,   // [3, V]: PD, T1, T2
                const float* __restrict__ TRp,
                float* __restrict__ out) {          // [V, NP2]
    __shared__ float2 f0s[WPB][VPW][NP2 + 1];       // +1 pad: conflict-free staging

    const int lane  = threadIdx.x & 31;
    const int wid   = threadIdx.x >> 5;
    const int sub   = lane >> 3;                    // voxel within warp
    const int ll    = lane & 7;                     // lane within voxel
    const int vbase = blockIdx.x * (WPB * VPW) + wid * VPW;
    const int v     = vbase + sub;

    const float TR = TRp[0];
    const float E1 = __expf(-TR / qmaps[NV + v]);
    const float E2 = __expf(-TR / qmaps[2 * NV + v]);
    const u64 E1p = bc(E1), E2p = bc(E2);
    const bool l0 = (ll == 0), l7 = (ll == 7);
    const u64 RecA = pk(l0 ? (1.0f - E1) : 0.0f, 0.0f);

    // State: F+ (P), F- (M), Z; each complex, 2 packed pairs per component.
    u64 Pr_a = 0, Pr_b = 0, Pi_a = 0, Pi_b = 0;
    u64 Mr_a = 0, Mr_b = 0, Mi_a = 0, Mi_b = 0;
    u64 Zr_a = pk(l0 ? 1.0f : 0.0f, 0.0f), Zr_b = 0, Zi_a = 0, Zi_b = 0;

    #pragma unroll 2
    for (int p = 0; p < NP2; p++) {
        const float4 c0 = g_c0[p], c1 = g_c1[p];
        const u64 Cca2  = bc(c0.x), Cca   = bc(c0.y);
        const u64 Cr10r = bc(c0.z), Cr10i = bc(c0.w), Cnr10i = bc(-c0.w);
        const u64 Cwr   = bc(c1.x), Cnwr  = bc(-c1.x), Cwi   = bc(c1.y);
        const u64 Chwr  = bc(c1.z), Cnhwr = bc(-c1.z), Cnhwi = bc(-c1.w);

        MATVEC(a)
        MATVEC(b)

        // unpack the pieces the shift needs
        float aPrL, aPrH, bPrL, bPrH, aPiL, aPiH, bPiL, bPiH;
        up(tPr_a, aPrL, aPrH); up(tPr_b, bPrL, bPrH);
        up(tPi_a, aPiL, aPiH); up(tPi_b, bPiL, bPiH);
        float aMrL, aMrH, bMrL, bMrH, aMiL, aMiH, bMiL, bMiH;
        up(tMr_a, aMrL, aMrH); up(tMr_b, bMrL, bMrH);
        up(tMi_a, aMiL, aMiH); up(tMi_b, bMiL, bMiH);

        // F0 signal = tP at k=0 (pre-relax/shift), one lane per voxel
        if (l0) f0s[wid][sub][p] = make_float2(aPrL, aPiL);

        // EPG shift: F+ up in k (boundary element from lane-1's k3),
        //            F- down in k (boundary element from lane+1's k0).
        float inPr = __shfl_up_sync(0xffffffffu, bPrH, 1);
        float inPi = __shfl_up_sync(0xffffffffu, bPiH, 1);
        float inMr = __shfl_down_sync(0xffffffffu, aMrL, 1);
        float inMi = __shfl_down_sync(0xffffffffu, aMiL, 1);
        if (l0) { inPr = aMrH; inPi = -aMiH; }   // F+_0 <- conj(F-_1)
        if (l7) { inMr = 0.0f; inMi = 0.0f; }    // F-_31 <- 0

        // relax (E2 on transverse, E1+recovery on longitudinal) + repack
        Pr_a = m2(E2p, pk(inPr, aPrL));  Pr_b = m2(E2p, pk(aPrH, bPrL));
        Pi_a = m2(E2p, pk(inPi, aPiL));  Pi_b = m2(E2p, pk(aPiH, bPiL));
        Mr_a = m2(E2p, pk(aMrH, bMrL));  Mr_b = m2(E2p, pk(bMrH, inMr));
        Mi_a = m2(E2p, pk(aMiH, bMiL));  Mi_b = m2(E2p, pk(bMiH, inMi));
        Zr_a = f2(E1p, tZr_a, RecA);     Zr_b = m2(E1p, tZr_b);
        Zi_a = m2(E1p, tZi_a);           Zi_b = m2(E1p, tZi_b);
    }

    __syncwarp();

    // Epilogue: |F0| * PD. 4 consecutive voxels per warp -> 256 contiguous
    // floats; fully coalesced 128B stores.
    const float* pdp = qmaps + vbase;
    float* ob = out + (size_t)vbase * NP2;
    #pragma unroll
    for (int i = 0; i < (VPW * NP2) / 32; i++) {
        int flat = i * 32 + lane;
        int vv   = flat >> 6;
        int idx  = flat & 63;
        float2 f = f0s[wid][vv][idx];
        ob[flat] = sqrtf(f.x * f.x + f.y * f.y) * pdp[vv];
    }
}

extern "C" void kernel_launch(void* const* d_in, const int* in_sizes, int n_in,
                              void* d_out, int out_size) {
    const float* theta_re = (const float*)d_in[0];   // [64]
    const float* theta_im = (const float*)d_in[1];   // [64]
    const float* TR       = (const float*)d_in[2];   // [1]
    const float* qmaps    = (const float*)d_in[3];   // [3, 32768, 1]
    float* out = (float*)d_out;                      // [32768, 64]

    precompute_coef_kernel<<<1, 64>>>(theta_re, theta_im);
    epg_kernel<<<NV / (WPB * VPW), WPB * 32>>>(qmaps, TR, out);
}

// round 3
// speedup vs baseline: 1.3148x; 1.0633x over previous
#include <cuda_runtime.h>
#include <math.h>

#define NP2 64
#define NV  32768
#define WPB 8            // warps per block
#define VPW 4            // voxels per warp
// 8 lanes per voxel, 4 k-states per lane (two f32x2 pairs per component)

typedef unsigned long long u64;

// Per-pulse coefficients, pre-broadcast as {x,x} f32 pairs, pre-negated.
// [p][0] = {ca2, sa2}  [p][1] = {ca, sa}  [p][2] = {-sa, hsa}
// [p][3] = {-hsa, cd}  [p][4] = {sd, -sd}      (cd,sd: cos/sin(phi_p - phi_{p+1}))
__device__ ulonglong2 g_cf[NP2][5];

__device__ __forceinline__ u64 dup_(float x) {
    u64 r; asm("mov.b64 %0,{%1,%1};" : "=l"(r) : "f"(x)); return r;
}

__global__ void precompute_coef_kernel(const float* __restrict__ thr,
                                       const float* __restrict__ thi) {
    int p = threadIdx.x;
    if (p >= NP2) return;
    float tr = thr[p], ti = thi[p];
    float a  = sqrtf(tr * tr + ti * ti);       // |theta| in (0.1, pi/2): never 0
    float inv_a = 1.0f / a;
    float cphi = tr * inv_a, sphi = ti * inv_a;
    float ca, sa;
    sincosf(a, &sa, &ca);
    float ca2 = 0.5f * (1.0f + ca);            // cos^2(a/2)
    float sa2 = 0.5f * (1.0f - ca);            // sin^2(a/2)
    float hsa = 0.5f * sa;

    // next pulse phase (delta twist); last pulse: delta = 0
    int pn = (p + 1 < NP2) ? p + 1 : p;
    float trn = thr[pn], tin = thi[pn];
    float an = sqrtf(trn * trn + tin * tin);
    float inv_an = 1.0f / an;
    float cphin = trn * inv_an, sphin = tin * inv_an;
    float cd = cphi * cphin + sphi * sphin;    // cos(phi_p - phi_{p+1})
    float sd = sphi * cphin - cphi * sphin;    // sin(phi_p - phi_{p+1})
    if (p + 1 >= NP2) { cd = 1.0f; sd = 0.0f; }

    g_cf[p][0] = make_ulonglong2(dup_(ca2),  dup_(sa2));
    g_cf[p][1] = make_ulonglong2(dup_(ca),   dup_(sa));
    g_cf[p][2] = make_ulonglong2(dup_(-sa),  dup_(hsa));
    g_cf[p][3] = make_ulonglong2(dup_(-hsa), dup_(cd));
    g_cf[p][4] = make_ulonglong2(dup_(sd),   dup_(-sd));
}

// ---- packed f32x2 helpers ----
__device__ __forceinline__ u64 bc(float x) {
    u64 r; asm("mov.b64 %0,{%1,%1};" : "=l"(r) : "f"(x)); return r;
}
__device__ __forceinline__ u64 pk(float a, float b) {
    u64 r; asm("mov.b64 %0,{%1,%2};" : "=l"(r) : "f"(a), "f"(b)); return r;
}
__device__ __forceinline__ void up(u64 v, float& a, float& b) {
    asm("mov.b64 {%0,%1},%2;" : "=f"(a), "=f"(b) : "l"(v));
}
__device__ __forceinline__ u64 f2(u64 a, u64 b, u64 c) {
    u64 d; asm("fma.rn.f32x2 %0,%1,%2,%3;" : "=l"(d) : "l"(a), "l"(b), "l"(c)); return d;
}
__device__ __forceinline__ u64 m2(u64 a, u64 b) {
    u64 d; asm("mul.rn.f32x2 %0,%1,%2;" : "=l"(d) : "l"(a), "l"(b)); return d;
}

// Phase-factored (phi=0) EPG matvec on a packed pair of k-states.
// A0 rows: [ca2, sa2, -i*sa; sa2, ca2, +i*sa; -i*hsa, +i*hsa, ca]
#define MATVEC(S) \
  u64 tPr_##S = f2(Cca2,Pr_##S, f2(Csa2,Mr_##S, m2(Csa ,Zi_##S))); \
  u64 tPi_##S = f2(Cca2,Pi_##S, f2(Csa2,Mi_##S, m2(Cnsa,Zr_##S))); \
  u64 tMr_##S = f2(Csa2,Pr_##S, f2(Cca2,Mr_##S, m2(Cnsa,Zi_##S))); \
  u64 tMi_##S = f2(Csa2,Pi_##S, f2(Cca2,Mi_##S, m2(Csa ,Zr_##S))); \
  u64 tZr_##S = f2(Cca ,Zr_##S, f2(Chsa ,Pi_##S, m2(Cnhsa,Mi_##S))); \
  u64 tZi_##S = f2(Cca ,Zi_##S, f2(Cnhsa,Pr_##S, m2(Chsa ,Mr_##S)));

// 4 voxels per warp, 8 lanes per voxel, 4 k-states per lane:
// lane ll (0..7) holds k = 4*ll + {0,1,2,3}; pair a = (k0,k1), pair b = (k2,k3).
__global__ __launch_bounds__(WPB * 32)
void epg_kernel(const float* __restrict__ qmaps,   // [3, V]: PD, T1, T2
                const float* __restrict__ TRp,
                float* __restrict__ out) {          // [V, NP2]
    __shared__ float2 f0s[WPB][VPW][NP2 + 1];

    const int lane  = threadIdx.x & 31;
    const int wid   = threadIdx.x >> 5;
    const int sub   = lane >> 3;                    // voxel within warp
    const int ll    = lane & 7;                     // lane within voxel
    const int vbase = blockIdx.x * (WPB * VPW) + wid * VPW;
    const int v     = vbase + sub;

    const float TR = TRp[0];
    const float E1 = __expf(-TR / qmaps[NV + v]);
    const float E2 = __expf(-TR / qmaps[2 * NV + v]);
    const u64 E1p = bc(E1), E2p = bc(E2);
    const bool l0 = (ll == 0), l7 = (ll == 7);
    const u64 RecA = pk(l0 ? (1.0f - E1) : 0.0f, 0.0f);

    // Twisted-frame state: F+ (P), F- (M), Z; complex, 2 packed pairs each.
    u64 Pr_a = 0, Pr_b = 0, Pi_a = 0, Pi_b = 0;
    u64 Mr_a = 0, Mr_b = 0, Mi_a = 0, Mi_b = 0;
    u64 Zr_a = pk(l0 ? 1.0f : 0.0f, 0.0f), Zr_b = 0, Zi_a = 0, Zi_b = 0;

    #pragma unroll 2
    for (int p = 0; p < NP2; p++) {
        const ulonglong2 q0 = g_cf[p][0];
        const ulonglong2 q1 = g_cf[p][1];
        const ulonglong2 q2 = g_cf[p][2];
        const ulonglong2 q3 = g_cf[p][3];
        const ulonglong2 q4 = g_cf[p][4];
        const u64 Cca2 = q0.x, Csa2 = q0.y;
        const u64 Cca  = q1.x, Csa  = q1.y;
        const u64 Cnsa = q2.x, Chsa = q2.y;
        const u64 Cnhsa = q3.x, Ccd = q3.y;
        const u64 Csd = q4.x, Cnsd = q4.y;
        // twist*relax multiplier u = E2 * e^{i(phi_p - phi_{p+1})}
        const u64 Ur  = m2(E2p, Ccd);
        const u64 Ui  = m2(E2p, Csd);
        const u64 Nui = m2(E2p, Cnsd);

        MATVEC(a)
        MATVEC(b)

        // unpack the pieces the shift needs
        float aPrL, aPrH, bPrL, bPrH, aPiL, aPiH, bPiL, bPiH;
        up(tPr_a, aPrL, aPrH); up(tPr_b, bPrL, bPrH);
        up(tPi_a, aPiL, aPiH); up(tPi_b, bPiL, bPiH);
        float aMrL, aMrH, bMrL, bMrH, aMiL, aMiH, bMiL, bMiH;
        up(tMr_a, aMrL, aMrH); up(tMr_b, bMrL, bMrH);
        up(tMi_a, aMiL, aMiH); up(tMi_b, bMiL, bMiH);

        // F0 = tP at k=0 pre-shift; frame phase drops under |.|
        if (l0) f0s[wid][sub][p] = make_float2(aPrL, aPiL);

        // EPG shift: F+ up in k, F- down in k; F+_0 <- conj(F-_1); F-_31 <- 0
        float inPr = __shfl_up_sync(0xffffffffu, bPrH, 1);
        float inPi = __shfl_up_sync(0xffffffffu, bPiH, 1);
        float inMr = __shfl_down_sync(0xffffffffu, aMrL, 1);
        float inMi = __shfl_down_sync(0xffffffffu, aMiL, 1);
        if (l0) { inPr = aMrH; inPi = -aMiH; }
        if (l7) { inMr = 0.0f; inMi = 0.0f; }

        // repack shifted values
        const u64 Xr_a = pk(inPr, aPrL), Xr_b = pk(aPrH, bPrL);
        const u64 Xi_a = pk(inPi, aPiL), Xi_b = pk(aPiH, bPiL);
        const u64 Yr_a = pk(aMrH, bMrL), Yr_b = pk(bMrH, inMr);
        const u64 Yi_a = pk(aMiH, bMiL), Yi_b = pk(bMiH, inMi);

        // twist+relax: P *= u, M *= conj(u), Z: E1 (+recovery)
        Pr_a = f2(Ur, Xr_a, m2(Nui, Xi_a));  Pr_b = f2(Ur, Xr_b, m2(Nui, Xi_b));
        Pi_a = f2(Ur, Xi_a, m2(Ui , Xr_a));  Pi_b = f2(Ur, Xi_b, m2(Ui , Xr_b));
        Mr_a = f2(Ur, Yr_a, m2(Ui , Yi_a));  Mr_b = f2(Ur, Yr_b, m2(Ui , Yi_b));
        Mi_a = f2(Ur, Yi_a, m2(Nui, Yr_a));  Mi_b = f2(Ur, Yi_b, m2(Nui, Yr_b));
        Zr_a = f2(E1p, tZr_a, RecA);         Zr_b = m2(E1p, tZr_b);
        Zi_a = m2(E1p, tZi_a);               Zi_b = m2(E1p, tZi_b);
    }

    __syncwarp();

    // Epilogue: |F0| * PD; 4 consecutive voxels per warp -> coalesced stores
    const float* pdp = qmaps + vbase;
    float* ob = out + (size_t)vbase * NP2;
    #pragma unroll
    for (int i = 0; i < (VPW * NP2) / 32; i++) {
        int flat = i * 32 + lane;
        int vv   = flat >> 6;
        int idx  = flat & 63;
        float2 f = f0s[wid][vv][idx];
        ob[flat] = sqrtf(f.x * f.x + f.y * f.y) * pdp[vv];
    }
}

extern "C" void kernel_launch(void* const* d_in, const int* in_sizes, int n_in,
                              void* d_out, int out_size) {
    const float* theta_re = (const float*)d_in[0];   // [64]
    const float* theta_im = (const float*)d_in[1];   // [64]
    const float* TR       = (const float*)d_in[2];   // [1]
    const float* qmaps    = (const float*)d_in[3];   // [3, 32768, 1]
    float* out = (float*)d_out;                      // [32768, 64]

    precompute_coef_kernel<<<1, 64>>>(theta_re, theta_im);
    epg_kernel<<<NV / (WPB * VPW), WPB * 32>>>(qmaps, TR, out);
}

// round 4
// speedup vs baseline: 1.3218x; 1.0053x over previous
#include <cuda_runtime.h>
#include <math.h>

#define NP2 64
#define NV  32768
#define WPB 8            // warps per block
#define VPW 4            // voxels per warp
// 8 lanes per voxel, 4 k-states per lane (two f32x2 pairs per component)

typedef unsigned long long u64;

// Per-pulse coefficients, pre-broadcast as {x,x} f32 pairs.
// [p][0] = {ca2, sa2}  [p][1] = {ca, sa}  [p][2] = {cd, sd}
__device__ ulonglong2 g_cf[NP2][3];

__device__ __forceinline__ u64 dup_(float x) {
    u64 r; asm("mov.b64 %0,{%1,%1};" : "=l"(r) : "f"(x)); return r;
}

__global__ void precompute_coef_kernel(const float* __restrict__ thr,
                                       const float* __restrict__ thi) {
    int p = threadIdx.x;
    if (p >= NP2) return;
    float tr = thr[p], ti = thi[p];
    float a  = sqrtf(tr * tr + ti * ti);       // |theta| in (0.1, pi/2): never 0
    float inv_a = 1.0f / a;
    float cphi = tr * inv_a, sphi = ti * inv_a;
    float ca, sa;
    sincosf(a, &sa, &ca);
    float ca2 = 0.5f * (1.0f + ca);            // cos^2(a/2)
    float sa2 = 0.5f * (1.0f - ca);            // sin^2(a/2)

    // next pulse phase (delta twist); last pulse: delta = 0
    int pn = (p + 1 < NP2) ? p + 1 : p;
    float trn = thr[pn], tin = thi[pn];
    float an = sqrtf(trn * trn + tin * tin);
    float inv_an = 1.0f / an;
    float cphin = trn * inv_an, sphin = tin * inv_an;
    float cd = cphi * cphin + sphi * sphin;    // cos(phi_p - phi_{p+1})
    float sd = sphi * cphin - cphi * sphin;    // sin(phi_p - phi_{p+1})
    if (p + 1 >= NP2) { cd = 1.0f; sd = 0.0f; }

    g_cf[p][0] = make_ulonglong2(dup_(ca2), dup_(sa2));
    g_cf[p][1] = make_ulonglong2(dup_(ca),  dup_(sa));
    g_cf[p][2] = make_ulonglong2(dup_(cd),  dup_(sd));
}

// ---- packed f32x2 helpers ----
__device__ __forceinline__ u64 bc(float x) {
    u64 r; asm("mov.b64 %0,{%1,%1};" : "=l"(r) : "f"(x)); return r;
}
__device__ __forceinline__ u64 pk(float a, float b) {
    u64 r; asm("mov.b64 %0,{%1,%2};" : "=l"(r) : "f"(a), "f"(b)); return r;
}
__device__ __forceinline__ void up(u64 v, float& a, float& b) {
    asm("mov.b64 {%0,%1},%2;" : "=f"(a), "=f"(b) : "l"(v));
}
__device__ __forceinline__ u64 f2(u64 a, u64 b, u64 c) {
    u64 d; asm("fma.rn.f32x2 %0,%1,%2,%3;" : "=l"(d) : "l"(a), "l"(b), "l"(c)); return d;
}
__device__ __forceinline__ u64 m2(u64 a, u64 b) {
    u64 d; asm("mul.rn.f32x2 %0,%1,%2;" : "=l"(d) : "l"(a), "l"(b)); return d;
}
__device__ __forceinline__ u64 s2(u64 a, u64 b) {
    u64 d; asm("sub.rn.f32x2 %0,%1,%2;" : "=l"(d) : "l"(a), "l"(b)); return d;
}

// Phase-factored (phi=0) EPG matvec on a packed pair of k-states.
// Negative-coefficient-free: shares qzr/qzi products, uses sub.
#define MATVEC(S) \
  u64 qzi_##S = m2(Csa, Zi_##S); \
  u64 qzr_##S = m2(Csa, Zr_##S); \
  u64 tPr_##S = f2(Cca2, Pr_##S, f2(Csa2, Mr_##S, qzi_##S)); \
  u64 tPi_##S = s2(f2(Cca2, Pi_##S, m2(Csa2, Mi_##S)), qzr_##S); \
  u64 tMr_##S = s2(f2(Csa2, Pr_##S, m2(Cca2, Mr_##S)), qzi_##S); \
  u64 tMi_##S = f2(Csa2, Pi_##S, f2(Cca2, Mi_##S, qzr_##S)); \
  u64 tZr_##S = f2(Cca, Zr_##S, m2(Chsa, s2(Pi_##S, Mi_##S))); \
  u64 tZi_##S = f2(Cca, Zi_##S, m2(Chsa, s2(Mr_##S, Pr_##S)));

// 4 voxels per warp, 8 lanes per voxel, 4 k-states per lane:
// lane ll (0..7) holds k = 4*ll + {0,1,2,3}; pair a = (k0,k1), pair b = (k2,k3).
__global__ __launch_bounds__(WPB * 32, 4)
void epg_kernel(const float* __restrict__ qmaps,   // [3, V]: PD, T1, T2
                const float* __restrict__ TRp,
                float* __restrict__ out) {          // [V, NP2]
    __shared__ float2 f0s[WPB][VPW][NP2 + 1];

    const int lane  = threadIdx.x & 31;
    const int wid   = threadIdx.x >> 5;
    const int sub   = lane >> 3;                    // voxel within warp
    const int ll    = lane & 7;                     // lane within voxel
    const int vbase = blockIdx.x * (WPB * VPW) + wid * VPW;
    const int v     = vbase + sub;

    const float TR = TRp[0];
    const float E1 = __expf(-TR / qmaps[NV + v]);
    const float E2 = __expf(-TR / qmaps[2 * NV + v]);
    const u64 E1p = bc(E1), E2p = bc(E2), nE2p = bc(-E2);
    const u64 HALFp = bc(0.5f);
    const bool l0 = (ll == 0), l7 = (ll == 7);
    const u64 RecA = pk(l0 ? (1.0f - E1) : 0.0f, 0.0f);

    // Twisted-frame state: F+ (P), F- (M), Z; complex, 2 packed pairs each.
    u64 Pr_a = 0, Pr_b = 0, Pi_a = 0, Pi_b = 0;
    u64 Mr_a = 0, Mr_b = 0, Mi_a = 0, Mi_b = 0;
    u64 Zr_a = pk(l0 ? 1.0f : 0.0f, 0.0f), Zr_b = 0, Zi_a = 0, Zi_b = 0;

    #pragma unroll 2
    for (int p = 0; p < NP2; p++) {
        const ulonglong2 q0 = g_cf[p][0];
        const ulonglong2 q1 = g_cf[p][1];
        const ulonglong2 q2 = g_cf[p][2];
        const u64 Cca2 = q0.x, Csa2 = q0.y;
        const u64 Cca  = q1.x, Csa  = q1.y;
        const u64 Chsa = m2(HALFp, Csa);        // 0.5*sa
        // twist*relax multiplier u = E2 * e^{i(phi_p - phi_{p+1})}
        const u64 Ur  = m2(E2p,  q2.x);
        const u64 Ui  = m2(E2p,  q2.y);
        const u64 Nui = m2(nE2p, q2.y);

        MATVEC(a)
        MATVEC(b)

        // unpack the pieces the shift needs
        float aPrL, aPrH, bPrL, bPrH, aPiL, aPiH, bPiL, bPiH;
        up(tPr_a, aPrL, aPrH); up(tPr_b, bPrL, bPrH);
        up(tPi_a, aPiL, aPiH); up(tPi_b, bPiL, bPiH);
        float aMrL, aMrH, bMrL, bMrH, aMiL, aMiH, bMiL, bMiH;
        up(tMr_a, aMrL, aMrH); up(tMr_b, bMrL, bMrH);
        up(tMi_a, aMiL, aMiH); up(tMi_b, bMiL, bMiH);

        // F0 = tP at k=0 pre-shift; frame phase drops under |.|
        if (l0) f0s[wid][sub][p] = make_float2(aPrL, aPiL);

        // EPG shift: F+ up in k, F- down in k; F+_0 <- conj(F-_1); F-_31 <- 0
        float inPr = __shfl_up_sync(0xffffffffu, bPrH, 1);
        float inPi = __shfl_up_sync(0xffffffffu, bPiH, 1);
        float inMr = __shfl_down_sync(0xffffffffu, aMrL, 1);
        float inMi = __shfl_down_sync(0xffffffffu, aMiL, 1);
        if (l0) { inPr = aMrH; inPi = -aMiH; }
        if (l7) { inMr = 0.0f; inMi = 0.0f; }

        // repack shifted values
        const u64 Xr_a = pk(inPr, aPrL), Xr_b = pk(aPrH, bPrL);
        const u64 Xi_a = pk(inPi, aPiL), Xi_b = pk(aPiH, bPiL);
        const u64 Yr_a = pk(aMrH, bMrL), Yr_b = pk(bMrH, inMr);
        const u64 Yi_a = pk(aMiH, bMiL), Yi_b = pk(bMiH, inMi);

        // twist+relax: P *= u, M *= conj(u), Z: E1 (+recovery)
        Pr_a = f2(Ur, Xr_a, m2(Nui, Xi_a));  Pr_b = f2(Ur, Xr_b, m2(Nui, Xi_b));
        Pi_a = f2(Ur, Xi_a, m2(Ui , Xr_a));  Pi_b = f2(Ur, Xi_b, m2(Ui , Xr_b));
        Mr_a = f2(Ur, Yr_a, m2(Ui , Yi_a));  Mr_b = f2(Ur, Yr_b, m2(Ui , Yi_b));
        Mi_a = f2(Ur, Yi_a, m2(Nui, Yr_a));  Mi_b = f2(Ur, Yi_b, m2(Nui, Yr_b));
        Zr_a = f2(E1p, tZr_a, RecA);         Zr_b = m2(E1p, tZr_b);
        Zi_a = m2(E1p, tZi_a);               Zi_b = m2(E1p, tZi_b);
    }

    __syncwarp();

    // Epilogue: |F0| * PD; 4 consecutive voxels per warp -> coalesced stores
    const float* pdp = qmaps + vbase;
    float* ob = out + (size_t)vbase * NP2;
    #pragma unroll
    for (int i = 0; i < (VPW * NP2) / 32; i++) {
        int flat = i * 32 + lane;
        int vv   = flat >> 6;
        int idx  = flat & 63;
        float2 f = f0s[wid][vv][idx];
        ob[flat] = sqrtf(f.x * f.x + f.y * f.y) * pdp[vv];
    }
}

extern "C" void kernel_launch(void* const* d_in, const int* in_sizes, int n_in,
                              void* d_out, int out_size) {
    const float* theta_re = (const float*)d_in[0];   // [64]
    const float* theta_im = (const float*)d_in[1];   // [64]
    const float* TR       = (const float*)d_in[2];   // [1]
    const float* qmaps    = (const float*)d_in[3];   // [3, 32768, 1]
    float* out = (float*)d_out;                      // [32768, 64]

    precompute_coef_kernel<<<1, 64>>>(theta_re, theta_im);
    epg_kernel<<<NV / (WPB * VPW), WPB * 32>>>(qmaps, TR, out);
}

// round 5
// speedup vs baseline: 1.4179x; 1.0727x over previous
#include <cuda_runtime.h>
#include <math.h>

#define NP2 64
#define NV  32768
#define WPB 4            // warps per block
#define VPW 4            // voxels per warp
// 8 lanes per voxel, 4 k-states per lane (two f32x2 pairs per component)

typedef unsigned long long u64;

// Per-pulse coefficients, pre-broadcast as {x,x} f32 pairs.
// [p][0]={ca2,sa2} [p][1]={ca,sa} [p][2]={hsa,cd} [p][3]={sd,-sd}
__device__ ulonglong2 g_cf[NP2][4];

__device__ __forceinline__ u64 dup_(float x) {
    u64 r; asm("mov.b64 %0,{%1,%1};" : "=l"(r) : "f"(x)); return r;
}

__global__ void precompute_coef_kernel(const float* __restrict__ thr,
                                       const float* __restrict__ thi) {
    int p = threadIdx.x;
    if (p >= NP2) return;
    float tr = thr[p], ti = thi[p];
    float a  = sqrtf(tr * tr + ti * ti);       // |theta| in (0.1, pi/2): never 0
    float inv_a = 1.0f / a;
    float cphi = tr * inv_a, sphi = ti * inv_a;
    float ca, sa;
    sincosf(a, &sa, &ca);
    float ca2 = 0.5f * (1.0f + ca);            // cos^2(a/2)
    float sa2 = 0.5f * (1.0f - ca);            // sin^2(a/2)
    float hsa = 0.5f * sa;

    // next pulse phase (delta twist); last pulse: delta = 0
    int pn = (p + 1 < NP2) ? p + 1 : p;
    float trn = thr[pn], tin = thi[pn];
    float an = sqrtf(trn * trn + tin * tin);
    float inv_an = 1.0f / an;
    float cphin = trn * inv_an, sphin = tin * inv_an;
    float cd = cphi * cphin + sphi * sphin;    // cos(phi_p - phi_{p+1})
    float sd = sphi * cphin - cphi * sphin;    // sin(phi_p - phi_{p+1})
    if (p + 1 >= NP2) { cd = 1.0f; sd = 0.0f; }

    g_cf[p][0] = make_ulonglong2(dup_(ca2), dup_(sa2));
    g_cf[p][1] = make_ulonglong2(dup_(ca),  dup_(sa));
    g_cf[p][2] = make_ulonglong2(dup_(hsa), dup_(cd));
    g_cf[p][3] = make_ulonglong2(dup_(sd),  dup_(-sd));
}

// ---- packed f32x2 helpers ----
__device__ __forceinline__ u64 bc(float x) {
    u64 r; asm("mov.b64 %0,{%1,%1};" : "=l"(r) : "f"(x)); return r;
}
__device__ __forceinline__ u64 pk(float a, float b) {
    u64 r; asm("mov.b64 %0,{%1,%2};" : "=l"(r) : "f"(a), "f"(b)); return r;
}
__device__ __forceinline__ void up(u64 v, float& a, float& b) {
    asm("mov.b64 {%0,%1},%2;" : "=f"(a), "=f"(b) : "l"(v));
}
__device__ __forceinline__ u64 f2(u64 a, u64 b, u64 c) {
    u64 d; asm("fma.rn.f32x2 %0,%1,%2,%3;" : "=l"(d) : "l"(a), "l"(b), "l"(c)); return d;
}
__device__ __forceinline__ u64 m2(u64 a, u64 b) {
    u64 d; asm("mul.rn.f32x2 %0,%1,%2;" : "=l"(d) : "l"(a), "l"(b)); return d;
}
__device__ __forceinline__ u64 s2(u64 a, u64 b) {
    u64 d; asm("sub.rn.f32x2 %0,%1,%2;" : "=l"(d) : "l"(a), "l"(b)); return d;
}
__device__ __forceinline__ u64 a2(u64 a, u64 b) {
    u64 d; asm("add.rn.f32x2 %0,%1,%2;" : "=l"(d) : "l"(a), "l"(b)); return d;
}

// Phase-factored EPG matvec with N = conj(F-) state (all-real coefficients):
//   tP = ca2 P + sa2 N + sa (i-free forms below)
//   tN = conj of M-row; tZ uses (Pi+Ni), (Nr-Pr).
#define MATVEC(S) \
  u64 qzi_##S = m2(Csa, Zi_##S); \
  u64 qzr_##S = m2(Csa, Zr_##S); \
  u64 tPr_##S = f2(Cca2, Pr_##S, f2(Csa2, Nr_##S, qzi_##S)); \
  u64 tPi_##S = s2(m2(Cca2, Pi_##S), f2(Csa2, Ni_##S, qzr_##S)); \
  u64 tNr_##S = s2(f2(Csa2, Pr_##S, m2(Cca2, Nr_##S)), qzi_##S); \
  u64 tNi_##S = s2(m2(Cca2, Ni_##S), f2(Csa2, Pi_##S, qzr_##S)); \
  u64 tZr_##S = f2(Cca, Zr_##S, m2(Chsa, a2(Pi_##S, Ni_##S))); \
  u64 tZi_##S = f2(Cca, Zi_##S, m2(Chsa, s2(Nr_##S, Pr_##S)));

// 4 voxels per warp, 8 lanes per voxel, 4 k-states per lane:
// lane ll (0..7) holds k = 4*ll + {0,1,2,3}; pair a = (k0,k1), pair b = (k2,k3).
__global__ __launch_bounds__(WPB * 32, 9)
void epg_kernel(const float* __restrict__ qmaps,   // [3, V]: PD, T1, T2
                const float* __restrict__ TRp,
                float* __restrict__ out) {          // [V, NP2]
    __shared__ ulonglong2 scf[NP2][4];              // 4KB coefficient table
    __shared__ float2 f0s[WPB][VPW][NP2 + 1];

    const int tid   = threadIdx.x;
    const int lane  = tid & 31;
    const int wid   = tid >> 5;
    const int sub   = lane >> 3;                    // voxel within warp
    const int ll    = lane & 7;                     // lane within voxel
    const int vbase = blockIdx.x * (WPB * VPW) + wid * VPW;
    const int v     = vbase + sub;

    // cooperative copy of the coefficient table (256 16B chunks, 128 threads)
    {
        const ulonglong2* src = &g_cf[0][0];
        ulonglong2* dst = &scf[0][0];
        dst[tid] = src[tid];
        dst[tid + 128] = src[tid + 128];
    }

    const float TR = TRp[0];
    const float E1 = __expf(-TR / qmaps[NV + v]);
    const float E2 = __expf(-TR / qmaps[2 * NV + v]);
    const u64 E1p = bc(E1), E2p = bc(E2);
    const bool l0 = (ll == 0), l7 = (ll == 7);
    const u64 RecA = pk(l0 ? (1.0f - E1) : 0.0f, 0.0f);

    // Twisted-frame state: F+ (P), N=conj(F-), Z; complex, 2 packed pairs each.
    u64 Pr_a = 0, Pr_b = 0, Pi_a = 0, Pi_b = 0;
    u64 Nr_a = 0, Nr_b = 0, Ni_a = 0, Ni_b = 0;
    u64 Zr_a = pk(l0 ? 1.0f : 0.0f, 0.0f), Zr_b = 0, Zi_a = 0, Zi_b = 0;

    __syncthreads();

    #pragma unroll 4
    for (int p = 0; p < NP2; p++) {
        const ulonglong2 q0 = scf[p][0];
        const ulonglong2 q1 = scf[p][1];
        const ulonglong2 q2 = scf[p][2];
        const ulonglong2 q3 = scf[p][3];
        const u64 Cca2 = q0.x, Csa2 = q0.y;
        const u64 Cca  = q1.x, Csa  = q1.y;
        const u64 Chsa = q2.x;
        // twist*relax multiplier u = E2 * e^{i(phi_p - phi_{p+1})}
        const u64 Ur  = m2(E2p, q2.y);
        const u64 Ui  = m2(E2p, q3.x);
        const u64 Nui = m2(E2p, q3.y);

        MATVEC(a)
        MATVEC(b)

        // unpack the pieces the shift needs
        float aPrL, aPrH, bPrL, bPrH, aPiL, aPiH, bPiL, bPiH;
        up(tPr_a, aPrL, aPrH); up(tPr_b, bPrL, bPrH);
        up(tPi_a, aPiL, aPiH); up(tPi_b, bPiL, bPiH);
        float aNrL, aNrH, bNrL, bNrH, aNiL, aNiH, bNiL, bNiH;
        up(tNr_a, aNrL, aNrH); up(tNr_b, bNrL, bNrH);
        up(tNi_a, aNiL, aNiH); up(tNi_b, bNiL, bNiH);

        // F0 = tP at k=0 pre-shift; frame phase drops under |.|
        if (l0) f0s[wid][sub][p] = make_float2(aPrL, aPiL);

        // EPG shift: F+ up in k, N (=conj F-) down in k;
        // boundary: P_0 <- N_1 (no conj needed!), N_31 <- 0.
        float inPr = __shfl_up_sync(0xffffffffu, bPrH, 1);
        float inPi = __shfl_up_sync(0xffffffffu, bPiH, 1);
        float inNr = __shfl_down_sync(0xffffffffu, aNrL, 1);
        float inNi = __shfl_down_sync(0xffffffffu, aNiL, 1);
        if (l0) { inPr = aNrH; inPi = aNiH; }
        if (l7) { inNr = 0.0f; inNi = 0.0f; }

        // repack shifted values
        const u64 Xr_a = pk(inPr, aPrL), Xr_b = pk(aPrH, bPrL);
        const u64 Xi_a = pk(inPi, aPiL), Xi_b = pk(aPiH, bPiL);
        const u64 Yr_a = pk(aNrH, bNrL), Yr_b = pk(bNrH, inNr);
        const u64 Yi_a = pk(aNiH, bNiL), Yi_b = pk(bNiH, inNi);

        // twist+relax: both P and N multiply by u (identical code paths);
        // Z: E1 (+recovery at k=0)
        Pr_a = f2(Ur, Xr_a, m2(Nui, Xi_a));  Pr_b = f2(Ur, Xr_b, m2(Nui, Xi_b));
        Pi_a = f2(Ur, Xi_a, m2(Ui , Xr_a));  Pi_b = f2(Ur, Xi_b, m2(Ui , Xr_b));
        Nr_a = f2(Ur, Yr_a, m2(Nui, Yi_a));  Nr_b = f2(Ur, Yr_b, m2(Nui, Yi_b));
        Ni_a = f2(Ur, Yi_a, m2(Ui , Yr_a));  Ni_b = f2(Ur, Yi_b, m2(Ui , Yr_b));
        Zr_a = f2(E1p, tZr_a, RecA);         Zr_b = m2(E1p, tZr_b);
        Zi_a = m2(E1p, tZi_a);               Zi_b = m2(E1p, tZi_b);
    }

    __syncwarp();

    // Epilogue: |F0| * PD; 4 consecutive voxels per warp -> coalesced stores
    const float* pdp = qmaps + vbase;
    float* ob = out + (size_t)vbase * NP2;
    #pragma unroll
    for (int i = 0; i < (VPW * NP2) / 32; i++) {
        int flat = i * 32 + lane;
        int vv   = flat >> 6;
        int idx  = flat & 63;
        float2 f = f0s[wid][vv][idx];
        ob[flat] = sqrtf(f.x * f.x + f.y * f.y) * pdp[vv];
    }
}

extern "C" void kernel_launch(void* const* d_in, const int* in_sizes, int n_in,
                              void* d_out, int out_size) {
    const float* theta_re = (const float*)d_in[0];   // [64]
    const float* theta_im = (const float*)d_in[1];   // [64]
    const float* TR       = (const float*)d_in[2];   // [1]
    const float* qmaps    = (const float*)d_in[3];   // [3, 32768, 1]
    float* out = (float*)d_out;                      // [32768, 64]

    precompute_coef_kernel<<<1, 64>>>(theta_re, theta_im);
    epg_kernel<<<NV / (WPB * VPW), WPB * 32>>>(qmaps, TR, out);
}